// round 9
// baseline (speedup 1.0000x reference)
#include <cuda_runtime.h>
#include <math.h>

#define N_NODES 100000
#define PAD     128
#define F_IN    512
#define DIM     32
#define NCLS    40
#define TM      128     // gemm1 rows per block
#define KT      64      // gemm1 k-tile
#define GEMM_BLOCKS ((N_NODES + TM - 1) / TM)

typedef unsigned long long u64;

#define FMA_F32X2(d, a, b, c) \
    asm("fma.rn.f32x2 %0, %1, %2, %3;" : "=l"(d) : "l"(a), "l"(b), "l"(c))
#define ADD_F32X2(d, a, b) \
    asm("add.rn.f32x2 %0, %1, %2;" : "=l"(d) : "l"(a), "l"(b))

__device__ __forceinline__ void unpack_f32x2(u64 v, float& lo, float& hi) {
    unsigned int l, h;
    asm("mov.b64 {%0, %1}, %2;" : "=r"(l), "=r"(h) : "l"(v));
    lo = __uint_as_float(l); hi = __uint_as_float(h);
}
__device__ __forceinline__ u64 pack_f32x2(float lo, float hi) {
    u64 r;
    asm("mov.b64 %0, {%1, %2};" : "=l"(r) : "r"(__float_as_uint(lo)), "r"(__float_as_uint(hi)));
    return r;
}

// ---------------- scratch (zero-initialized at module load) ----------------
__device__ int   g_cur[N_NODES];                    // scatter cursor; self-cleaned each run
__device__ int   g_deg[N_NODES];                    // in-degree (excl. self loop)
__device__ float g_dinv[N_NODES];
__device__ int   g_bucket[(size_t)N_NODES * PAD];
__device__ float g_xws[(size_t)N_NODES * DIM];      // raw x@W1, then scaled in-place
__device__ float g_hs [(size_t)N_NODES * DIM];
__device__ float g_z  [(size_t)N_NODES * DIM];

// =================== fused: scatter (blocks [0,nsb)) || gemm1 (rest) =========
__global__ __launch_bounds__(256) void k_main(const float* __restrict__ x,
                                              const float* __restrict__ W1,
                                              const void*  __restrict__ ei,
                                              int E, int nsb) {
    if (blockIdx.x < nsb) {
        // ---------------- scatter: 2 edges per thread ----------------
        int lane = threadIdx.x & 31;
        // local dtype detect: int64 values < 2^31 -> all odd 32-bit words zero
        int probe = ((const int*)ei)[2 * lane + 1];
        unsigned nzm = __ballot_sync(0xffffffffu, probe != 0);
        int is64 = (nzm == 0);

        int t = blockIdx.x * blockDim.x + threadIdx.x;
        int e0 = t * 2;
        if (e0 >= E) return;
        int s0, s1, d0, d1;
        bool two = (e0 + 1 < E);
        if (!(E & 1)) {
            if (is64) {
                const longlong2* p = (const longlong2*)ei;
                longlong2 sv = p[t];
                longlong2 dv = p[(E >> 1) + t];
                s0 = (int)sv.x; s1 = (int)sv.y;
                d0 = (int)dv.x; d1 = (int)dv.y;
            } else {
                const int2* p = (const int2*)ei;
                int2 sv = p[t];
                int2 dv = p[(E >> 1) + t];
                s0 = sv.x; s1 = sv.y;
                d0 = dv.x; d1 = dv.y;
            }
        } else {   // odd E: scalar fallback
            if (is64) {
                const long long* p = (const long long*)ei;
                s0 = (int)p[e0]; d0 = (int)p[(size_t)E + e0];
                s1 = two ? (int)p[e0 + 1] : 0;
                d1 = two ? (int)p[(size_t)E + e0 + 1] : -1;
            } else {
                const int* p = (const int*)ei;
                s0 = p[e0]; d0 = p[E + e0];
                s1 = two ? p[e0 + 1] : 0;
                d1 = two ? p[E + e0 + 1] : -1;
            }
        }
        if ((unsigned)d0 < N_NODES && (unsigned)s0 < N_NODES) {
            int p0 = atomicAdd(&g_cur[d0], 1);
            if (p0 < PAD) g_bucket[(size_t)d0 * PAD + p0] = s0;
        }
        if (two && (unsigned)d1 < N_NODES && (unsigned)s1 < N_NODES) {
            int p1 = atomicAdd(&g_cur[d1], 1);
            if (p1 < PAD) g_bucket[(size_t)d1 * PAD + p1] = s1;
        }
    } else {
        // ---------------- gemm1: raw xw = x @ W1 (no dinv yet) ----------------
        __shared__ float xs[TM][KT];
        __shared__ float wt[DIM][KT + 2];
        int t = threadIdx.x;
        int row0 = (blockIdx.x - nsb) * TM;

        int rt = t >> 4, ct = t & 15;
        int r0 = rt * 8, c0 = ct * 2;

        u64 acc[8][2];
#pragma unroll
        for (int i = 0; i < 8; i++) { acc[i][0] = 0ull; acc[i][1] = 0ull; }

        for (int kc = 0; kc < F_IN; kc += KT) {
            __syncthreads();
#pragma unroll
            for (int i = 0; i < 8; i++) {
                int lin = t + i * 256;
                int row = lin >> 4, f4 = lin & 15;
                int grow = row0 + row;
                float4 v = make_float4(0.f, 0.f, 0.f, 0.f);
                if (grow < N_NODES)
                    v = *(const float4*)&x[(size_t)grow * F_IN + kc + f4 * 4];
                *(float4*)&xs[row][f4 * 4] = v;
            }
#pragma unroll
            for (int i = 0; i < 8; i++) {
                int lin = t + i * 256;
                int k = lin >> 5, col = lin & 31;
                wt[col][k] = W1[(size_t)(kc + k) * DIM + col];
            }
            __syncthreads();

#pragma unroll 4
            for (int kp = 0; kp < KT / 2; kp++) {
                u64 wv0 = *(const u64*)&wt[c0][kp * 2];
                u64 wv1 = *(const u64*)&wt[c0 + 1][kp * 2];
#pragma unroll
                for (int i = 0; i < 8; i++) {
                    u64 xv = *(const u64*)&xs[r0 + i][kp * 2];
                    FMA_F32X2(acc[i][0], xv, wv0, acc[i][0]);
                    FMA_F32X2(acc[i][1], xv, wv1, acc[i][1]);
                }
            }
        }
#pragma unroll
        for (int i = 0; i < 8; i++) {
            int row = row0 + r0 + i;
            if (row < N_NODES) {
                float l0, h0, l1, h1;
                unpack_f32x2(acc[i][0], l0, h0);
                unpack_f32x2(acc[i][1], l1, h1);
                *(float2*)&g_xws[(size_t)row * DIM + c0] =
                    make_float2(l0 + h0, l1 + h1);
            }
        }
    }
}

// =================== dinv + in-place scale + deg copy + cursor reset =========
__global__ void k_scale() {
    int gw   = (blockIdx.x * blockDim.x + threadIdx.x) >> 5;
    int lane = threadIdx.x & 31;
    int h    = lane >> 4, hl = lane & 15;
    int node = gw * 2 + h;
    if (node >= N_NODES) return;

    int cnt  = g_cur[node];
    float di = rsqrtf((float)(cnt + 1));
    u64* p = (u64*)g_xws + (size_t)node * 16 + hl;
    float lo, hi;
    unpack_f32x2(*p, lo, hi);
    *p = pack_f32x2(di * lo, di * hi);
    if (hl == 0) {
        g_dinv[node] = di;
        g_deg[node]  = cnt;
        g_cur[node]  = 0;       // self-clean for next replay
    }
}

// =================== aggregation (half-warp per node, f32x2 lanes) ===========
template <int LAYER>
__global__ void k_agg(const float* __restrict__ bias) {
    const float* __restrict__ in  = (LAYER == 1) ? g_xws : g_hs;
    float* __restrict__       out = (LAYER == 1) ? g_hs  : g_z;
    const u64* __restrict__   in2 = (const u64*)in;

    int gw   = (blockIdx.x * blockDim.x + threadIdx.x) >> 5;
    int lane = threadIdx.x & 31;
    int h    = lane >> 4, hl = lane & 15;
    int node = gw * 2 + h;
    if (node >= N_NODES) return;

    float di = g_dinv[node];
    u64 s = in2[(size_t)node * 16 + hl];
    int cnt = g_deg[node];
    if (cnt > PAD) cnt = PAD;
    const int* bkt = g_bucket + (size_t)node * PAD;

    int cnt4 = cnt & ~3;
    int cnt4max = max(cnt4, __shfl_xor_sync(0xffffffffu, cnt4, 16));

    for (int e = 0; e < cnt4max; e += 4) {
        if (e < cnt4) {
            int4 ia = *(const int4*)(bkt + e);     // 1 LDG.128 per 4 edges
            u64 v0 = in2[(size_t)ia.x * 16 + hl];
            u64 v1 = in2[(size_t)ia.y * 16 + hl];
            u64 v2 = in2[(size_t)ia.z * 16 + hl];
            u64 v3 = in2[(size_t)ia.w * 16 + hl];
            ADD_F32X2(s, s, v0);
            ADD_F32X2(s, s, v1);
            ADD_F32X2(s, s, v2);
            ADD_F32X2(s, s, v3);
        }
    }
    for (int r = cnt4; r < cnt; r++) {             // <=3 tail edges
        u64 v = in2[(size_t)bkt[r] * 16 + hl];
        ADD_F32X2(s, s, v);
    }

    float lo, hi;
    unpack_f32x2(s, lo, hi);
    float* op = out + (size_t)node * DIM + hl * 2;
    if (LAYER == 1) {
        float2 bp = ((const float2*)bias)[hl];
        float h0 = fmaxf(fmaf(di, lo, bp.x), 0.f);
        float h1 = fmaxf(fmaf(di, hi, bp.y), 0.f);
        op[0] = di * h0;
        op[1] = di * h1;
    } else {
        op[0] = di * lo;
        op[1] = di * hi;
    }
}

// =================== GEMM2 (32x40) + log_softmax, warp per node ==============
__global__ void k_out(const float* __restrict__ W2, const float* __restrict__ b2,
                      float* __restrict__ out) {
    __shared__ float W2s[DIM * NCLS];
    __shared__ float b2s[NCLS];
    int t = threadIdx.x;
    for (int i = t; i < DIM * NCLS; i += blockDim.x) W2s[i] = W2[i];
    if (t < NCLS) b2s[t] = b2[t];
    __syncthreads();

    int node = (blockIdx.x * blockDim.x + t) >> 5;
    if (node >= N_NODES) return;
    int lane = t & 31;

    float zv = g_z[(size_t)node * DIM + lane];
    int k2 = (lane < NCLS - 32) ? (lane + 32) : lane;
    float a1 = 0.f, a2 = 0.f;
#pragma unroll
    for (int c = 0; c < DIM; c++) {
        float zc = __shfl_sync(0xffffffffu, zv, c);
        a1 = fmaf(zc, W2s[c * NCLS + lane], a1);
        a2 = fmaf(zc, W2s[c * NCLS + k2],   a2);
    }
    float l1 = a1 + b2s[lane];
    float l2 = a2 + b2s[k2];
    bool has2 = (lane < NCLS - 32);

    float m = has2 ? fmaxf(l1, l2) : l1;
#pragma unroll
    for (int o = 16; o > 0; o >>= 1) m = fmaxf(m, __shfl_xor_sync(0xffffffffu, m, o));

    float esum = __expf(l1 - m) + (has2 ? __expf(l2 - m) : 0.f);
#pragma unroll
    for (int o = 16; o > 0; o >>= 1) esum += __shfl_xor_sync(0xffffffffu, esum, o);

    float ls = m + __logf(esum);
    out[(size_t)node * NCLS + lane] = l1 - ls;
    if (has2) out[(size_t)node * NCLS + 32 + lane] = l2 - ls;
}

// =================== launch ==================================================
extern "C" void kernel_launch(void* const* d_in, const int* in_sizes, int n_in,
                              void* d_out, int out_size) {
    const float* x  = (const float*)d_in[0];
    const void*  ei = d_in[1];
    const float* W1 = (const float*)d_in[2];
    const float* b1 = (const float*)d_in[3];
    const float* W2 = (const float*)d_in[4];
    const float* b2 = (const float*)d_in[5];
    float*       out = (float*)d_out;

    int E = in_sizes[1] / 2;
    int nsb = ((E + 1) / 2 + 255) / 256;   // scatter blocks (2 edges/thread)

    k_main<<<nsb + GEMM_BLOCKS, 256>>>(x, W1, ei, E, nsb);
    k_scale<<<6250, 256>>>();
    k_agg<1><<<6250, 256>>>(b1);
    k_agg<2><<<6250, 256>>>(b1);
    k_out<<<12500, 256>>>(W2, b2, out);
}

// round 11
// speedup vs baseline: 1.0349x; 1.0349x over previous
#include <cuda_runtime.h>
#include <math.h>

#define N_NODES 100000
#define PAD     128
#define F_IN    512
#define DIM     32
#define NCLS    40
#define TM      128     // gemm1 rows per block
#define KT      32      // gemm1 k-tile (double buffered)
#define NTILES  (F_IN / KT)
#define GEMM_BLOCKS ((N_NODES + TM - 1) / TM)

typedef unsigned long long u64;

#define FMA_F32X2(d, a, b, c) \
    asm("fma.rn.f32x2 %0, %1, %2, %3;" : "=l"(d) : "l"(a), "l"(b), "l"(c))
#define ADD_F32X2(d, a, b) \
    asm("add.rn.f32x2 %0, %1, %2;" : "=l"(d) : "l"(a), "l"(b))

__device__ __forceinline__ void unpack_f32x2(u64 v, float& lo, float& hi) {
    unsigned int l, h;
    asm("mov.b64 {%0, %1}, %2;" : "=r"(l), "=r"(h) : "l"(v));
    lo = __uint_as_float(l); hi = __uint_as_float(h);
}
__device__ __forceinline__ u64 pack_f32x2(float lo, float hi) {
    u64 r;
    asm("mov.b64 %0, {%1, %2};" : "=l"(r) : "r"(__float_as_uint(lo)), "r"(__float_as_uint(hi)));
    return r;
}
__device__ __forceinline__ unsigned smem_u32(const void* p) {
    return (unsigned)__cvta_generic_to_shared(p);
}
#define CP_ASYNC16(dst, src) \
    asm volatile("cp.async.cg.shared.global [%0], [%1], 16;" :: "r"(dst), "l"(src))
#define CP_COMMIT()  asm volatile("cp.async.commit_group;" ::: "memory")
#define CP_WAIT_1()  asm volatile("cp.async.wait_group 1;" ::: "memory")
#define CP_WAIT_0()  asm volatile("cp.async.wait_group 0;" ::: "memory")

// ---------------- scratch (zero-initialized at module load) ----------------
__device__ int   g_cur[N_NODES];                    // scatter cursor; self-cleaned each run
__device__ int   g_deg[N_NODES];
__device__ float g_dinv[N_NODES];
__device__ int   g_bucket[(size_t)N_NODES * PAD];
__device__ float g_xws[(size_t)N_NODES * DIM];      // raw x@W1, then scaled in-place
__device__ float g_hs [(size_t)N_NODES * DIM];
__device__ float g_z  [(size_t)N_NODES * DIM];

// =================== fused: scatter (blocks [0,nsb)) || gemm1 (rest) =========
__global__ __launch_bounds__(256) void k_main(const float* __restrict__ x,
                                              const float* __restrict__ W1,
                                              const void*  __restrict__ ei,
                                              int E, int nsb) {
    if (blockIdx.x < nsb) {
        // ---------------- scatter: 2 edges per thread ----------------
        int lane = threadIdx.x & 31;
        int probe = ((const int*)ei)[2 * lane + 1];
        unsigned nzm = __ballot_sync(0xffffffffu, probe != 0);
        int is64 = (nzm == 0);

        int t = blockIdx.x * blockDim.x + threadIdx.x;
        int e0 = t * 2;
        if (e0 >= E) return;
        int s0, s1, d0, d1;
        bool two = (e0 + 1 < E);
        if (!(E & 1)) {
            if (is64) {
                const longlong2* p = (const longlong2*)ei;
                longlong2 sv = p[t];
                longlong2 dv = p[(E >> 1) + t];
                s0 = (int)sv.x; s1 = (int)sv.y;
                d0 = (int)dv.x; d1 = (int)dv.y;
            } else {
                const int2* p = (const int2*)ei;
                int2 sv = p[t];
                int2 dv = p[(E >> 1) + t];
                s0 = sv.x; s1 = sv.y;
                d0 = dv.x; d1 = dv.y;
            }
        } else {
            if (is64) {
                const long long* p = (const long long*)ei;
                s0 = (int)p[e0]; d0 = (int)p[(size_t)E + e0];
                s1 = two ? (int)p[e0 + 1] : 0;
                d1 = two ? (int)p[(size_t)E + e0 + 1] : -1;
            } else {
                const int* p = (const int*)ei;
                s0 = p[e0]; d0 = p[E + e0];
                s1 = two ? p[e0 + 1] : 0;
                d1 = two ? p[E + e0 + 1] : -1;
            }
        }
        if ((unsigned)d0 < N_NODES && (unsigned)s0 < N_NODES) {
            int p0 = atomicAdd(&g_cur[d0], 1);
            if (p0 < PAD) g_bucket[(size_t)d0 * PAD + p0] = s0;
        }
        if (two && (unsigned)d1 < N_NODES && (unsigned)s1 < N_NODES) {
            int p1 = atomicAdd(&g_cur[d1], 1);
            if (p1 < PAD) g_bucket[(size_t)d1 * PAD + p1] = s1;
        }
    } else {
        // ---------- gemm1: raw xw = x @ W1, double-buffered cp.async ----------
        __shared__ float xs[2][TM][KT];       // 2 x 16 KB
        __shared__ float wr[2][KT][DIM];      // 2 x 4 KB raw [k][col]
        __shared__ float wt[2][DIM][KT + 2];  // 2 x 4.25 KB transposed
        int t = threadIdx.x;
        int row0 = (blockIdx.x - nsb) * TM;

        int rt = t >> 4, ct = t & 15;
        int r0 = rt * 8, c0 = ct * 2;

        // per-thread load slots: 2 threads per row, each covers 16 floats (4 x float4)
        int xrow = t >> 1;                   // 0..127
        int xf   = (t & 1) * 16;             // float offset within row: 0 or 16
        int grow = row0 + xrow;
        if (grow >= N_NODES) grow = N_NODES - 1;   // clamp; results discarded
        const float* xsrc = x + (size_t)grow * F_IN + xf;

        u64 acc[8][2];
#pragma unroll
        for (int i = 0; i < 8; i++) { acc[i][0] = 0ull; acc[i][1] = 0ull; }

        // issue loads for tile `tile` into buffer `b`
        auto load_tile = [&](int tile, int b) {
            int kc = tile * KT;
            // x: row = 32 floats (128B); this thread's half = 16 floats = 4 float4
            unsigned dst0 = smem_u32(&xs[b][xrow][xf]);
            const float* src = xsrc + kc;
            CP_ASYNC16(dst0,      src);
            CP_ASYNC16(dst0 + 16, src + 4);
            CP_ASYNC16(dst0 + 32, src + 8);
            CP_ASYNC16(dst0 + 48, src + 12);
            // w raw: 32x32 floats = 256 float4; thread t loads one
            int wk = t >> 3, wc = (t & 7) * 4;
            CP_ASYNC16(smem_u32(&wr[b][wk][wc]), W1 + (size_t)(kc + wk) * DIM + wc);
        };

        load_tile(0, 0);
        CP_COMMIT();

        for (int tile = 0; tile < NTILES; tile++) {
            int b = tile & 1;
            if (tile + 1 < NTILES) { load_tile(tile + 1, b ^ 1); CP_COMMIT(); CP_WAIT_1(); }
            else                   { CP_WAIT_0(); }
            __syncthreads();

            // transpose w for this buffer: 1024 floats, 4 per thread
#pragma unroll
            for (int i = 0; i < 4; i++) {
                int lin = t + i * 256;
                int k = lin >> 5, col = lin & 31;
                wt[b][col][k] = wr[b][k][col];
            }
            __syncthreads();

#pragma unroll 4
            for (int kp = 0; kp < KT / 2; kp++) {
                u64 wv0 = *(const u64*)&wt[b][c0][kp * 2];
                u64 wv1 = *(const u64*)&wt[b][c0 + 1][kp * 2];
#pragma unroll
                for (int i = 0; i < 8; i++) {
                    u64 xv = *(const u64*)&xs[b][r0 + i][kp * 2];
                    FMA_F32X2(acc[i][0], xv, wv0, acc[i][0]);
                    FMA_F32X2(acc[i][1], xv, wv1, acc[i][1]);
                }
            }
            __syncthreads();
        }

#pragma unroll
        for (int i = 0; i < 8; i++) {
            int row = row0 + r0 + i;
            if (row < N_NODES) {
                float l0, h0, l1, h1;
                unpack_f32x2(acc[i][0], l0, h0);
                unpack_f32x2(acc[i][1], l1, h1);
                *(float2*)&g_xws[(size_t)row * DIM + c0] =
                    make_float2(l0 + h0, l1 + h1);
            }
        }
    }
}

// =================== dinv + in-place scale + deg copy + cursor reset =========
__global__ void k_scale() {
    int gw   = (blockIdx.x * blockDim.x + threadIdx.x) >> 5;
    int lane = threadIdx.x & 31;
    int h    = lane >> 4, hl = lane & 15;
    int node = gw * 2 + h;
    if (node >= N_NODES) return;

    int cnt  = g_cur[node];
    float di = rsqrtf((float)(cnt + 1));
    u64* p = (u64*)g_xws + (size_t)node * 16 + hl;
    float lo, hi;
    unpack_f32x2(*p, lo, hi);
    *p = pack_f32x2(di * lo, di * hi);
    if (hl == 0) {
        g_dinv[node] = di;
        g_deg[node]  = cnt;
        g_cur[node]  = 0;       // self-clean for next replay
    }
}

// =================== aggregation (half-warp per node, f32x2 lanes) ===========
template <int LAYER>
__global__ void k_agg(const float* __restrict__ bias) {
    const float* __restrict__ in  = (LAYER == 1) ? g_xws : g_hs;
    float* __restrict__       out = (LAYER == 1) ? g_hs  : g_z;
    const u64* __restrict__   in2 = (const u64*)in;

    int gw   = (blockIdx.x * blockDim.x + threadIdx.x) >> 5;
    int lane = threadIdx.x & 31;
    int h    = lane >> 4, hl = lane & 15;
    int node = gw * 2 + h;
    if (node >= N_NODES) return;

    float di = g_dinv[node];
    u64 s = in2[(size_t)node * 16 + hl];
    int cnt = g_deg[node];
    if (cnt > PAD) cnt = PAD;
    const int* bkt = g_bucket + (size_t)node * PAD;

    int cnt4 = cnt & ~3;
    int cnt4max = max(cnt4, __shfl_xor_sync(0xffffffffu, cnt4, 16));

    for (int e = 0; e < cnt4max; e += 4) {
        if (e < cnt4) {
            int4 ia = *(const int4*)(bkt + e);
            u64 v0 = in2[(size_t)ia.x * 16 + hl];
            u64 v1 = in2[(size_t)ia.y * 16 + hl];
            u64 v2 = in2[(size_t)ia.z * 16 + hl];
            u64 v3 = in2[(size_t)ia.w * 16 + hl];
            ADD_F32X2(s, s, v0);
            ADD_F32X2(s, s, v1);
            ADD_F32X2(s, s, v2);
            ADD_F32X2(s, s, v3);
        }
    }
    for (int r = cnt4; r < cnt; r++) {
        u64 v = in2[(size_t)bkt[r] * 16 + hl];
        ADD_F32X2(s, s, v);
    }

    float lo, hi;
    unpack_f32x2(s, lo, hi);
    float* op = out + (size_t)node * DIM + hl * 2;
    if (LAYER == 1) {
        float2 bp = ((const float2*)bias)[hl];
        float h0 = fmaxf(fmaf(di, lo, bp.x), 0.f);
        float h1 = fmaxf(fmaf(di, hi, bp.y), 0.f);
        op[0] = di * h0;
        op[1] = di * h1;
    } else {
        op[0] = di * lo;
        op[1] = di * hi;
    }
}

// =================== GEMM2 (32x40) + log_softmax, warp per node ==============
__global__ void k_out(const float* __restrict__ W2, const float* __restrict__ b2,
                      float* __restrict__ out) {
    __shared__ float W2s[DIM * NCLS];
    __shared__ float b2s[NCLS];
    int t = threadIdx.x;
    for (int i = t; i < DIM * NCLS; i += blockDim.x) W2s[i] = W2[i];
    if (t < NCLS) b2s[t] = b2[t];
    __syncthreads();

    int node = (blockIdx.x * blockDim.x + t) >> 5;
    if (node >= N_NODES) return;
    int lane = t & 31;

    float zv = g_z[(size_t)node * DIM + lane];
    int k2 = (lane < NCLS - 32) ? (lane + 32) : lane;
    float a1 = 0.f, a2 = 0.f;
#pragma unroll
    for (int c = 0; c < DIM; c++) {
        float zc = __shfl_sync(0xffffffffu, zv, c);
        a1 = fmaf(zc, W2s[c * NCLS + lane], a1);
        a2 = fmaf(zc, W2s[c * NCLS + k2],   a2);
    }
    float l1 = a1 + b2s[lane];
    float l2 = a2 + b2s[k2];
    bool has2 = (lane < NCLS - 32);

    float m = has2 ? fmaxf(l1, l2) : l1;
#pragma unroll
    for (int o = 16; o > 0; o >>= 1) m = fmaxf(m, __shfl_xor_sync(0xffffffffu, m, o));

    float esum = __expf(l1 - m) + (has2 ? __expf(l2 - m) : 0.f);
#pragma unroll
    for (int o = 16; o > 0; o >>= 1) esum += __shfl_xor_sync(0xffffffffu, esum, o);

    float ls = m + __logf(esum);
    out[(size_t)node * NCLS + lane] = l1 - ls;
    if (has2) out[(size_t)node * NCLS + 32 + lane] = l2 - ls;
}

// =================== launch ==================================================
extern "C" void kernel_launch(void* const* d_in, const int* in_sizes, int n_in,
                              void* d_out, int out_size) {
    const float* x  = (const float*)d_in[0];
    const void*  ei = d_in[1];
    const float* W1 = (const float*)d_in[2];
    const float* b1 = (const float*)d_in[3];
    const float* W2 = (const float*)d_in[4];
    const float* b2 = (const float*)d_in[5];
    float*       out = (float*)d_out;

    int E = in_sizes[1] / 2;
    int nsb = ((E + 1) / 2 + 255) / 256;

    k_main<<<nsb + GEMM_BLOCKS, 256>>>(x, W1, ei, E, nsb);
    k_scale<<<6250, 256>>>();
    k_agg<1><<<6250, 256>>>(b1);
    k_agg<2><<<6250, 256>>>(b1);
    k_out<<<12500, 256>>>(W2, b2, out);
}